// round 17
// baseline (speedup 1.0000x reference)
#include <cuda_runtime.h>
#include <cuda_bf16.h>

#define FEAT_C 512
#define FEAT_H 100
#define FEAT_W 152
#define NUM_ROIS 512
#define AH 14
#define AW 14
#define SPATIAL_SCALE 0.0625f
#define CH_CHUNK 32
#define CHUNKS_PER_ROI (FEAT_C / CH_CHUNK)   // 16
#define BINS (AH * AW)                       // 196
#define HW (FEAT_H * FEAT_W)

// v10: class-split kernels.
//  FAST kernel (nx<=16, ~48% of rois): lean 2-shuffle body small enough to
//    fit 32 regs -> launch_bounds(224,9) targets 9 blocks/SM (~98% occ) to
//    close the latency-hiding gap (L1 70% @ occ 60% in v9).
//  SLOW kernel (nx>16): R7 body at the proven (224,6)/40-reg config.
//  Both early-exit on the other class (cheap); both CH_CHUNK=32, chunk-major.

struct RoiXParams {
    int   nx, x_lo;
    float x_start, y_start, bin_h, bin_w;
    int   b;
};

__device__ __forceinline__ RoiXParams roi_decode(const float* __restrict__ rois, int r)
{
    RoiXParams p;
    const float* rp = rois + r * 5;
    p.b       = (int)rp[0];
    p.x_start = rp[1] * SPATIAL_SCALE;
    p.y_start = rp[2] * SPATIAL_SCALE;
    const float x_end = rp[3] * SPATIAL_SCALE;
    const float y_end = rp[4] * SPATIAL_SCALE;
    const float roi_w = fmaxf(x_end - p.x_start, 0.0f);
    const float roi_h = fmaxf(y_end - p.y_start, 0.0f);
    p.bin_h = roi_h * (1.0f / (float)(AH - 1));
    p.bin_w = roi_w * (1.0f / (float)(AW - 1));
    const float xs0c = fminf(fmaxf(p.x_start, 0.0f), (float)(FEAT_W - 1));
    const float xsEc = fminf(fmaxf(x_end,     0.0f), (float)(FEAT_W - 1));
    p.x_lo = (int)floorf(xs0c);
    const int x_hi = min((int)floorf(xsEc) + 1, FEAT_W - 1);
    p.nx = x_hi - p.x_lo + 1;
    return p;
}

// ===================== FAST KERNEL: nx <= 16, 32-reg target =====================
__global__ __launch_bounds__(224, 9) void roi_align_fast(
    const float* __restrict__ feat,
    const float* __restrict__ rois,
    float* __restrict__ out)
{
    const int r     = blockIdx.x & (NUM_ROIS - 1);
    const int chunk = blockIdx.x >> 9;
    const int c0    = chunk * CH_CHUNK;

    const RoiXParams P = roi_decode(rois, r);
    if (P.nx > 16) return;                               // other class

    const int tid  = threadIdx.x;
    const int wid  = tid >> 5;
    const int lane = tid & 31;

    // per-lane x interp
    const int pw = (lane < 16) ? min(lane, AW - 1) : min(lane - 16, AW - 1);
    float xs = P.x_start + (float)pw * P.bin_w;
    xs = fminf(fmaxf(xs, 0.0f), (float)(FEAT_W - 1));
    const int   x0  = (int)floorf(xs);
    const int   sx0 = x0 - P.x_lo;
    const int   sx1 = min(x0 + 1, FEAT_W - 1) - P.x_lo;
    const float wx  = xs - (float)x0;
    const int   src0 = (lane & 16) | sx0;
    const int   src1 = (lane & 16) | sx1;

    // per-warp y (this lane's half)
    const int ph_a = wid * 2;
    const bool hi  = (lane >= 16);
    float ysl = P.y_start + (float)(ph_a + (hi ? 1 : 0)) * P.bin_h;
    ysl = fminf(fmaxf(ysl, 0.0f), (float)(FEAT_H - 1));
    const int   y0l = (int)floorf(ysl);
    const int   y1l = min(y0l + 1, FEAT_H - 1);
    const float wyl = ysl - (float)y0l;
    const int   ro0 = y0l * FEAT_W;
    const int   ro1 = y1l * FEAT_W;

    const int col_off = min(lane & 15, P.nx - 1);
    const float* base = feat + ((size_t)P.b * FEAT_C + c0) * HW + P.x_lo + col_off;

    float* op = out + ((size_t)r * FEAT_C + c0) * BINS + ph_a * AW;
    const bool stok = (lane < 14) || (lane >= 16 && lane < 30);
    const int  soff = (lane < 14) ? lane : (lane - 2);

    #pragma unroll
    for (int cc = 0; cc < CH_CHUNK; cc += 2) {
        const float* fA = base + cc * HW;
        const float* fB = fA + HW;

        const float Ar0 = __ldg(fA + ro0);
        const float Ar1 = __ldg(fA + ro1);
        const float Br0 = __ldg(fB + ro0);
        const float Br1 = __ldg(fB + ro1);

        const float Am = fmaf(wyl, Ar1 - Ar0, Ar0);
        const float Bm = fmaf(wyl, Br1 - Br0, Br0);

        const float As0 = __shfl_sync(0xffffffffu, Am, src0);
        const float As1 = __shfl_sync(0xffffffffu, Am, src1);
        const float Bs0 = __shfl_sync(0xffffffffu, Bm, src0);
        const float Bs1 = __shfl_sync(0xffffffffu, Bm, src1);

        const float Av = fmaf(wx, As1 - As0, As0);
        const float Bv = fmaf(wx, Bs1 - Bs0, Bs0);

        if (stok) {
            op[cc * BINS + soff]       = Av;
            op[(cc + 1) * BINS + soff] = Bv;
        }
    }
}

// ===================== SLOW KERNEL: nx > 16, proven 40-reg config ===============
__global__ __launch_bounds__(224, 6) void roi_align_slow(
    const float* __restrict__ feat,
    const float* __restrict__ rois,
    float* __restrict__ out)
{
    const int r     = blockIdx.x & (NUM_ROIS - 1);
    const int chunk = blockIdx.x >> 9;
    const int c0    = chunk * CH_CHUNK;

    const RoiXParams P = roi_decode(rois, r);
    if (P.nx <= 16) return;                              // other class

    const int tid  = threadIdx.x;
    const int wid  = tid >> 5;
    const int lane = tid & 31;

    // per-lane x interp
    const int pw = (lane < 16) ? min(lane, AW - 1) : min(lane - 16, AW - 1);
    float xs = P.x_start + (float)pw * P.bin_w;
    xs = fminf(fmaxf(xs, 0.0f), (float)(FEAT_W - 1));
    const int   x0  = (int)floorf(xs);
    const int   x1  = min(x0 + 1, FEAT_W - 1);
    const float wx  = xs - (float)x0;
    const int   sx0 = x0 - P.x_lo;
    const int   sx1 = x1 - P.x_lo;

    // per-warp y params (both rows)
    const int ph_a = wid * 2;
    float ysa = P.y_start + (float)ph_a * P.bin_h;
    float ysb = P.y_start + (float)(ph_a + 1) * P.bin_h;
    ysa = fminf(fmaxf(ysa, 0.0f), (float)(FEAT_H - 1));
    ysb = fminf(fmaxf(ysb, 0.0f), (float)(FEAT_H - 1));
    const int   ya0 = (int)floorf(ysa);
    const int   ya1 = min(ya0 + 1, FEAT_H - 1);
    const float wya = ysa - (float)ya0;
    const int   yb0 = (int)floorf(ysb);
    const int   yb1 = min(yb0 + 1, FEAT_H - 1);
    const float wyb = ysb - (float)yb0;
    const bool  reuse = (yb0 == ya1);

    const float* base = feat + ((size_t)P.b * FEAT_C + c0) * HW + P.x_lo;
    const int oa0 = ya0 * FEAT_W, oa1 = ya1 * FEAT_W;
    const int ob0 = yb0 * FEAT_W, ob1 = yb1 * FEAT_W;

    float* op = out + ((size_t)r * FEAT_C + c0) * BINS + ph_a * AW;
    const bool stok = (lane < 14) || (lane >= 16 && lane < 30);
    const int  soff = (lane < 14) ? lane : (lane - 2);
    const bool ldok = (lane < P.nx);

    #pragma unroll
    for (int cc = 0; cc < CH_CHUNK; cc++) {
        const float* f = base + cc * HW;
        float ra0 = ldok ? __ldg(f + oa0 + lane) : 0.0f;
        float ra1 = ldok ? __ldg(f + oa1 + lane) : 0.0f;
        float rb1 = ldok ? __ldg(f + ob1 + lane) : 0.0f;
        float rb0;
        if (reuse) {
            rb0 = ra1;
        } else {
            rb0 = ldok ? __ldg(f + ob0 + lane) : 0.0f;
        }

        const float la = fmaf(wya, ra1 - ra0, ra0);
        const float lb = fmaf(wyb, rb1 - rb0, rb0);

        const float a0 = __shfl_sync(0xffffffffu, la, sx0);
        const float a1 = __shfl_sync(0xffffffffu, la, sx1);
        const float b0 = __shfl_sync(0xffffffffu, lb, sx0);
        const float b1 = __shfl_sync(0xffffffffu, lb, sx1);

        const float s0 = (lane < 16) ? a0 : b0;
        const float s1 = (lane < 16) ? a1 : b1;
        const float v  = fmaf(wx, s1 - s0, s0);

        if (stok) op[cc * BINS + soff] = v;
    }
}

extern "C" void kernel_launch(void* const* d_in, const int* in_sizes, int n_in,
                              void* d_out, int out_size)
{
    const float* feat = (const float*)d_in[0];
    const float* rois = (const float*)d_in[1];
    float* out = (float*)d_out;

    dim3 grid(NUM_ROIS * CHUNKS_PER_ROI);   // 8192, chunk-major
    dim3 block(224);
    roi_align_fast<<<grid, block>>>(feat, rois, out);
    roi_align_slow<<<grid, block>>>(feat, rois, out);
}